// round 16
// baseline (speedup 1.0000x reference)
#include <cuda_runtime.h>
#include <cuda_fp16.h>
#include <cstdint>
#include <cstddef>

// ---------------------------------------------------------------------------
// Problem dims (fixed by the dataset)
// ---------------------------------------------------------------------------
#define T_TOK 16384           // 16 * 1024 tokens
#define H_DIM 1152            // K
#define O_DIM 4608            // N

// ---------------------------------------------------------------------------
// GEMM tiling: R13 structure + loader-warp split (warps 0-3 load, 4-7 start
// MMA immediately post-barrier). CTA 128x128x64, 8 warps, 3 stages, 2 CTA/SM.
// ---------------------------------------------------------------------------
#define BM 128
#define BN 128
#define BK 64                 // 64 halves = 128 B per row (full SW128 period)
#define NSTAGES 3
#define KITERS (H_DIM / BK)   // 18
#define TILE_BYTES (BM * BK * 2)            // 16384 (A), same for B
#define STAGE_BYTES (2 * TILE_BYTES)        // 32768
#define SMEM_TOTAL (NSTAGES * STAGE_BYTES)  // 98304

// fused prep kernel split
#define QBLKS (T_TOK / 8)                          // 2048 quant blocks (8 tok/blk)
#define WCONV_BLOCKS (O_DIM * H_DIM / (256 * 4))   // 5184 exactly

// Swizzle<3,4,3>: bits[6:4] ^= bits[9:7]
#define SWZ(o) ((o) ^ (((o) >> 3) & 0x70))

// ---------------------------------------------------------------------------
// Scratch (device globals: no runtime allocation allowed)
// ---------------------------------------------------------------------------
__device__ __align__(1024) __half g_A[(size_t)T_TOK * H_DIM];  // quantized acts
__device__ __align__(1024) __half g_W[(size_t)O_DIM * H_DIM];  // fp16 weights

// ---------------------------------------------------------------------------
// PTX helpers (all sm_80-era, safe under compute_103)
// ---------------------------------------------------------------------------
__device__ __forceinline__ uint32_t smem_u32(const void* p) {
    return (uint32_t)__cvta_generic_to_shared(p);
}

#define CP_ASYNC16(dst, src) \
    asm volatile("cp.async.cg.shared.global [%0], [%1], 16;" :: "r"(dst), "l"(src))
#define CP_ASYNC_COMMIT() asm volatile("cp.async.commit_group;" ::: "memory")
#define CP_ASYNC_WAIT(n)  asm volatile("cp.async.wait_group %0;" :: "n"(n) : "memory")

__device__ __forceinline__ void ldsm_x4(uint32_t& r0, uint32_t& r1, uint32_t& r2,
                                        uint32_t& r3, uint32_t addr) {
    asm volatile("ldmatrix.sync.aligned.m8n8.x4.shared.b16 {%0,%1,%2,%3}, [%4];"
                 : "=r"(r0), "=r"(r1), "=r"(r2), "=r"(r3) : "r"(addr));
}

__device__ __forceinline__ void mma16816(float& d0, float& d1, float& d2, float& d3,
                                         uint32_t a0, uint32_t a1, uint32_t a2,
                                         uint32_t a3, uint32_t b0, uint32_t b1) {
    asm volatile(
        "mma.sync.aligned.m16n8k16.row.col.f32.f16.f16.f32 "
        "{%0,%1,%2,%3}, {%4,%5,%6,%7}, {%8,%9}, {%0,%1,%2,%3};"
        : "+f"(d0), "+f"(d1), "+f"(d2), "+f"(d3)
        : "r"(a0), "r"(a1), "r"(a2), "r"(a3), "r"(b0), "r"(b1));
}

// ---------------------------------------------------------------------------
// Kernel 1 (fused prep):
//   quant blocks [0, QBLKS): warp-per-token NVFP4 fake-quant -> fp16 A.
//     The per-token pre_scale cancels algebraically: level is decided by
//     n = 6|v|/blockmax and the output scale is blockmax/6 (differs from the
//     reference chain only by ~1ulp rounding and measure-zero ties).
//     No smem, no __syncthreads, 2 shfls per block-16.
//   wconv blocks [QBLKS, +WCONV_BLOCKS): W fp32 -> fp16 streaming.
// ---------------------------------------------------------------------------
__global__ void __launch_bounds__(256) prep_kernel(const float* __restrict__ x,
                                                   const float* __restrict__ smooth,
                                                   const float* __restrict__ w) {
    const int tid = threadIdx.x;

    if (blockIdx.x >= QBLKS) {
        // ---- wconv part ----
        int i = ((blockIdx.x - QBLKS) * 256 + tid) * 4;
        float4 f = __ldcs(reinterpret_cast<const float4*>(w + i));
        __half2* p = reinterpret_cast<__half2*>(g_W + i);
        p[0] = __floats2half2_rn(f.x, f.y);
        p[1] = __floats2half2_rn(f.z, f.w);
        return;
    }

    // ---- quant part: one warp = one token ----
    const int l = tid & 31;
    const size_t t = (size_t)blockIdx.x * 8 + (tid >> 5);
    const float* xr = x + t * H_DIM;

    float v[9][4];
    float bm[9];
#pragma unroll
    for (int c = 0; c < 9; c++) {
        float4 xv = *reinterpret_cast<const float4*>(xr + c * 128 + l * 4);
        float4 sv = *reinterpret_cast<const float4*>(smooth + c * 128 + l * 4);
        v[c][0] = __fmul_rn(xv.x, sv.x);
        v[c][1] = __fmul_rn(xv.y, sv.y);
        v[c][2] = __fmul_rn(xv.z, sv.z);
        v[c][3] = __fmul_rn(xv.w, sv.w);
        float a = fmaxf(fmaxf(fabsf(v[c][0]), fabsf(v[c][1])),
                        fmaxf(fabsf(v[c][2]), fabsf(v[c][3])));
        // block of 16 = 4 adjacent lanes at this chunk
        a = fmaxf(a, __shfl_xor_sync(0xffffffffu, a, 1));
        a = fmaxf(a, __shfl_xor_sync(0xffffffffu, a, 2));
        bm[c] = a;
    }

    __half* arow = g_A + t * H_DIM;
#pragma unroll
    for (int c = 0; c < 9; c++) {
        float bmc = fmaxf(bm[c], 1e-30f);
        float r6  = __fdiv_rn(6.0f, bmc);               // n = |v| * 6/bm
        float sp  = __fmul_rn(bmc, 0.16666667f);        // out scale = bm/6
        __half q[4];
#pragma unroll
        for (int e = 0; e < 4; e++) {
            float n = __fmul_rn(fabsf(v[c][e]), r6);    // in [0, 6]
            float s  = (n <= 2.0f) ? 0.5f : (n <= 4.0f) ? 1.0f : 2.0f;
            float rs = (n <= 2.0f) ? 2.0f : (n <= 4.0f) ? 1.0f : 0.5f;
            float level = __fmul_rn(rintf(__fmul_rn(n, rs)), s);
            q[e] = __float2half_rn(__fmul_rn(copysignf(level, v[c][e]), sp));
        }
        *reinterpret_cast<uint2*>(arow + c * 128 + l * 4) =
            *reinterpret_cast<uint2*>(q);
    }
}

// ---------------------------------------------------------------------------
// Kernel 2: fp16 mma.sync GEMM (R13 structure + loader-warp split)
// out[m,n] = sum_k A[m,k]*W[n,k] + bias[n]
// ---------------------------------------------------------------------------
__device__ __forceinline__ void load_stage(uint32_t sbase, int st, int kt,
                                           int m0, int n0, int tid) {
    // only threads 0..127 (warps 0-3, one per SMSP) issue loads
    const uint32_t sA = sbase + st * STAGE_BYTES;
    const uint32_t sB = sA + TILE_BYTES;
    const __half* Ag = g_A + (size_t)m0 * H_DIM + kt * BK;
    const __half* Bg = g_W + (size_t)n0 * H_DIM + kt * BK;
#pragma unroll
    for (int i = 0; i < 8; i++) {          // A: 1024 x 16B granules
        int g = tid + i * 128;
        int r = g >> 3, c = g & 7;
        uint32_t off = SWZ((uint32_t)(r * 128 + c * 16));
        CP_ASYNC16(sA + off, Ag + (size_t)r * H_DIM + c * 8);
    }
#pragma unroll
    for (int i = 0; i < 8; i++) {          // B: 1024 x 16B granules
        int g = tid + i * 128;
        int r = g >> 3, c = g & 7;
        uint32_t off = SWZ((uint32_t)(r * 128 + c * 16));
        CP_ASYNC16(sB + off, Bg + (size_t)r * H_DIM + c * 8);
    }
}

__global__ void __launch_bounds__(256, 2) gemm_kernel(const float* __restrict__ bias,
                                                      float* __restrict__ out) {
    extern __shared__ char smem[];
    const uint32_t sbase = smem_u32(smem);
    const int tid = threadIdx.x;
    const int wid = tid >> 5;
    const int lid = tid & 31;
    const int wm = wid & 1;        // 2 warp rows  (64 M each)
    const int wn = wid >> 1;       // 4 warp cols  (32 N each)
    const int m0 = blockIdx.y * BM;
    const int n0 = blockIdx.x * BN;
    const bool loader = (tid < 128);

    float acc[4][4][4];
#pragma unroll
    for (int i = 0; i < 4; i++)
#pragma unroll
        for (int j = 0; j < 4; j++)
#pragma unroll
            for (int e = 0; e < 4; e++) acc[i][j][e] = 0.0f;

    // ldmatrix per-lane base byte offsets within a tile (row stride 128 B)
    const uint32_t a_base = (uint32_t)(wm * 64 + (lid & 15)) * 128 +
                            (uint32_t)(lid >> 4) * 16;
    const uint32_t b_base = (uint32_t)(wn * 32 + ((lid >> 3) & 2) * 4 + (lid & 7)) * 128 +
                            (uint32_t)((lid >> 3) & 1) * 16;

    // prologue: stages 0,1
#pragma unroll
    for (int p = 0; p < NSTAGES - 1; p++) {
        if (loader) load_stage(sbase, p, p, m0, n0, tid);
        CP_ASYNC_COMMIT();
    }

    int st = 0;
    for (int kt = 0; kt < KITERS; kt++) {
        CP_ASYNC_WAIT(NSTAGES - 2);
        __syncthreads();

        // refill the stage freed one iteration ago (readers done pre-barrier);
        // only warps 0-3 issue loads, warps 4-7 proceed straight to MMA
        const int nk = kt + NSTAGES - 1;
        int nst = st - 1; if (nst < 0) nst += NSTAGES;
        if (loader && nk < KITERS) load_stage(sbase, nst, nk, m0, n0, tid);
        CP_ASYNC_COMMIT();

        const uint32_t sA = sbase + st * STAGE_BYTES;
        const uint32_t sB = sA + TILE_BYTES;
#pragma unroll
        for (int ks = 0; ks < BK / 16; ks++) {   // 4 k16 steps
            uint32_t a[4][4];
#pragma unroll
            for (int mi = 0; mi < 4; mi++) {
                uint32_t o = a_base + (uint32_t)mi * (16 * 128) + (uint32_t)ks * 32;
                ldsm_x4(a[mi][0], a[mi][1], a[mi][2], a[mi][3], sA + SWZ(o));
            }
            uint32_t b[4][2];
#pragma unroll
            for (int p = 0; p < 2; p++) {  // each covers n-frags 2p, 2p+1
                uint32_t o = b_base + (uint32_t)p * (16 * 128) + (uint32_t)ks * 32;
                uint32_t r0, r1, r2, r3;
                ldsm_x4(r0, r1, r2, r3, sB + SWZ(o));
                b[2 * p][0] = r0; b[2 * p][1] = r1;
                b[2 * p + 1][0] = r2; b[2 * p + 1][1] = r3;
            }
#pragma unroll
            for (int mi = 0; mi < 4; mi++)
#pragma unroll
                for (int ni = 0; ni < 4; ni++)
                    mma16816(acc[mi][ni][0], acc[mi][ni][1],
                             acc[mi][ni][2], acc[mi][ni][3],
                             a[mi][0], a[mi][1], a[mi][2], a[mi][3],
                             b[ni][0], b[ni][1]);
        }
        st++; if (st == NSTAGES) st = 0;
    }

    // epilogue: fused bias, fp32 stores
    const int tr = lid >> 2;       // 0..7
    const int tc = lid & 3;        // 0..3
    const int mb = m0 + wm * 64;
    const int nb = n0 + wn * 32;
    float2 bv[4];
#pragma unroll
    for (int ni = 0; ni < 4; ni++)
        bv[ni] = *reinterpret_cast<const float2*>(bias + nb + ni * 8 + tc * 2);
#pragma unroll
    for (int mi = 0; mi < 4; mi++) {
        float* r0 = out + (size_t)(mb + mi * 16 + tr) * O_DIM + nb;
        float* r1 = r0 + (size_t)8 * O_DIM;
#pragma unroll
        for (int ni = 0; ni < 4; ni++) {
            float2 v0, v1;
            v0.x = acc[mi][ni][0] + bv[ni].x;
            v0.y = acc[mi][ni][1] + bv[ni].y;
            v1.x = acc[mi][ni][2] + bv[ni].x;
            v1.y = acc[mi][ni][3] + bv[ni].y;
            *reinterpret_cast<float2*>(r0 + ni * 8 + tc * 2) = v0;
            *reinterpret_cast<float2*>(r1 + ni * 8 + tc * 2) = v1;
        }
    }
}

// ---------------------------------------------------------------------------
// Launch
// ---------------------------------------------------------------------------
extern "C" void kernel_launch(void* const* d_in, const int* in_sizes, int n_in,
                              void* d_out, int out_size) {
    const float* x      = (const float*)d_in[0];  // [16,1024,1152]
    const float* w      = (const float*)d_in[1];  // [4608,1152]
    const float* smooth = (const float*)d_in[2];  // [1152]
    const float* bias   = (const float*)d_in[3];  // [4608]
    float* out = (float*)d_out;                   // [16,1024,4608]

    prep_kernel<<<QBLKS + WCONV_BLOCKS, 256>>>(x, smooth, w);

    cudaFuncSetAttribute(gemm_kernel, cudaFuncAttributeMaxDynamicSharedMemorySize,
                         SMEM_TOTAL);
    dim3 grid(O_DIM / BN, T_TOK / BM);   // (36, 128)
    gemm_kernel<<<grid, 256, SMEM_TOTAL>>>(bias, out);
}

// round 17
// speedup vs baseline: 1.0128x; 1.0128x over previous
#include <cuda_runtime.h>
#include <cuda_fp16.h>
#include <cstdint>
#include <cstddef>

// ---------------------------------------------------------------------------
// Problem dims (fixed by the dataset)
// ---------------------------------------------------------------------------
#define T_TOK 16384           // 16 * 1024 tokens
#define H_DIM 1152            // K
#define O_DIM 4608            // N

// ---------------------------------------------------------------------------
// GEMM tiling: exact R13 structure (best measured GEMM: 404.9us).
// CTA 128x128x64, 8 warps (2 M x 4 N), warp tile 64x32, 3 stages, 2 CTAs/SM.
// ---------------------------------------------------------------------------
#define BM 128
#define BN 128
#define BK 64                 // 64 halves = 128 B per row (full SW128 period)
#define NSTAGES 3
#define KITERS (H_DIM / BK)   // 18
#define TILE_BYTES (BM * BK * 2)            // 16384 (A), same for B
#define STAGE_BYTES (2 * TILE_BYTES)        // 32768
#define SMEM_TOTAL (NSTAGES * STAGE_BYTES)  // 98304

// fused prep kernel split (R16 version: best measured prep, ~28.4us)
#define QBLKS (T_TOK / 8)                          // 2048 quant blocks (8 tok/blk)
#define WCONV_BLOCKS (O_DIM * H_DIM / (256 * 4))   // 5184 exactly

// Swizzle<3,4,3>: bits[6:4] ^= bits[9:7]
#define SWZ(o) ((o) ^ (((o) >> 3) & 0x70))

// ---------------------------------------------------------------------------
// Scratch (device globals: no runtime allocation allowed)
// ---------------------------------------------------------------------------
__device__ __align__(1024) __half g_A[(size_t)T_TOK * H_DIM];  // quantized acts
__device__ __align__(1024) __half g_W[(size_t)O_DIM * H_DIM];  // fp16 weights

// ---------------------------------------------------------------------------
// PTX helpers (all sm_80-era, safe under compute_103)
// ---------------------------------------------------------------------------
__device__ __forceinline__ uint32_t smem_u32(const void* p) {
    return (uint32_t)__cvta_generic_to_shared(p);
}

#define CP_ASYNC16(dst, src) \
    asm volatile("cp.async.cg.shared.global [%0], [%1], 16;" :: "r"(dst), "l"(src))
#define CP_ASYNC_COMMIT() asm volatile("cp.async.commit_group;" ::: "memory")
#define CP_ASYNC_WAIT(n)  asm volatile("cp.async.wait_group %0;" :: "n"(n) : "memory")

__device__ __forceinline__ void ldsm_x4(uint32_t& r0, uint32_t& r1, uint32_t& r2,
                                        uint32_t& r3, uint32_t addr) {
    asm volatile("ldmatrix.sync.aligned.m8n8.x4.shared.b16 {%0,%1,%2,%3}, [%4];"
                 : "=r"(r0), "=r"(r1), "=r"(r2), "=r"(r3) : "r"(addr));
}

__device__ __forceinline__ void mma16816(float& d0, float& d1, float& d2, float& d3,
                                         uint32_t a0, uint32_t a1, uint32_t a2,
                                         uint32_t a3, uint32_t b0, uint32_t b1) {
    asm volatile(
        "mma.sync.aligned.m16n8k16.row.col.f32.f16.f16.f32 "
        "{%0,%1,%2,%3}, {%4,%5,%6,%7}, {%8,%9}, {%0,%1,%2,%3};"
        : "+f"(d0), "+f"(d1), "+f"(d2), "+f"(d3)
        : "r"(a0), "r"(a1), "r"(a2), "r"(a3), "r"(b0), "r"(b1));
}

// ---------------------------------------------------------------------------
// Kernel 1 (fused prep):
//   quant blocks [0, QBLKS): warp-per-token NVFP4 fake-quant -> fp16 A.
//     The per-token pre_scale cancels algebraically: level is decided by
//     n = 6|v|/blockmax and the output scale is blockmax/6 (differs from the
//     reference chain only by ~1ulp rounding and measure-zero ties).
//   wconv blocks [QBLKS, +WCONV_BLOCKS): W fp32 -> fp16 streaming.
// ---------------------------------------------------------------------------
__global__ void __launch_bounds__(256) prep_kernel(const float* __restrict__ x,
                                                   const float* __restrict__ smooth,
                                                   const float* __restrict__ w) {
    const int tid = threadIdx.x;

    if (blockIdx.x >= QBLKS) {
        // ---- wconv part ----
        int i = ((blockIdx.x - QBLKS) * 256 + tid) * 4;
        float4 f = __ldcs(reinterpret_cast<const float4*>(w + i));
        __half2* p = reinterpret_cast<__half2*>(g_W + i);
        p[0] = __floats2half2_rn(f.x, f.y);
        p[1] = __floats2half2_rn(f.z, f.w);
        return;
    }

    // ---- quant part: one warp = one token ----
    const int l = tid & 31;
    const size_t t = (size_t)blockIdx.x * 8 + (tid >> 5);
    const float* xr = x + t * H_DIM;

    float v[9][4];
    float bm[9];
#pragma unroll
    for (int c = 0; c < 9; c++) {
        float4 xv = *reinterpret_cast<const float4*>(xr + c * 128 + l * 4);
        float4 sv = *reinterpret_cast<const float4*>(smooth + c * 128 + l * 4);
        v[c][0] = __fmul_rn(xv.x, sv.x);
        v[c][1] = __fmul_rn(xv.y, sv.y);
        v[c][2] = __fmul_rn(xv.z, sv.z);
        v[c][3] = __fmul_rn(xv.w, sv.w);
        float a = fmaxf(fmaxf(fabsf(v[c][0]), fabsf(v[c][1])),
                        fmaxf(fabsf(v[c][2]), fabsf(v[c][3])));
        // block of 16 = 4 adjacent lanes at this chunk
        a = fmaxf(a, __shfl_xor_sync(0xffffffffu, a, 1));
        a = fmaxf(a, __shfl_xor_sync(0xffffffffu, a, 2));
        bm[c] = a;
    }

    __half* arow = g_A + t * H_DIM;
#pragma unroll
    for (int c = 0; c < 9; c++) {
        float bmc = fmaxf(bm[c], 1e-30f);
        float r6  = __fdiv_rn(6.0f, bmc);               // n = |v| * 6/bm
        float sp  = __fmul_rn(bmc, 0.16666667f);        // out scale = bm/6
        __half q[4];
#pragma unroll
        for (int e = 0; e < 4; e++) {
            float n = __fmul_rn(fabsf(v[c][e]), r6);    // in [0, 6]
            float s  = (n <= 2.0f) ? 0.5f : (n <= 4.0f) ? 1.0f : 2.0f;
            float rs = (n <= 2.0f) ? 2.0f : (n <= 4.0f) ? 1.0f : 0.5f;
            float level = __fmul_rn(rintf(__fmul_rn(n, rs)), s);
            q[e] = __float2half_rn(__fmul_rn(copysignf(level, v[c][e]), sp));
        }
        *reinterpret_cast<uint2*>(arow + c * 128 + l * 4) =
            *reinterpret_cast<uint2*>(q);
    }
}

// ---------------------------------------------------------------------------
// Kernel 2: fp16 mma.sync GEMM (exact R13 structure)
// out[m,n] = sum_k A[m,k]*W[n,k] + bias[n]
// ---------------------------------------------------------------------------
__device__ __forceinline__ void load_stage(uint32_t sbase, int st, int kt,
                                           int m0, int n0, int tid) {
    const uint32_t sA = sbase + st * STAGE_BYTES;
    const uint32_t sB = sA + TILE_BYTES;
    const __half* Ag = g_A + (size_t)m0 * H_DIM + kt * BK;
    const __half* Bg = g_W + (size_t)n0 * H_DIM + kt * BK;
#pragma unroll
    for (int i = 0; i < 4; i++) {          // A: 1024 x 16B granules
        int g = tid + i * 256;
        int r = g >> 3, c = g & 7;
        uint32_t off = SWZ((uint32_t)(r * 128 + c * 16));
        CP_ASYNC16(sA + off, Ag + (size_t)r * H_DIM + c * 8);
    }
#pragma unroll
    for (int i = 0; i < 4; i++) {          // B: 1024 x 16B granules
        int g = tid + i * 256;
        int r = g >> 3, c = g & 7;
        uint32_t off = SWZ((uint32_t)(r * 128 + c * 16));
        CP_ASYNC16(sB + off, Bg + (size_t)r * H_DIM + c * 8);
    }
}

__global__ void __launch_bounds__(256, 2) gemm_kernel(const float* __restrict__ bias,
                                                      float* __restrict__ out) {
    extern __shared__ char smem[];
    const uint32_t sbase = smem_u32(smem);
    const int tid = threadIdx.x;
    const int wid = tid >> 5;
    const int lid = tid & 31;
    const int wm = wid & 1;        // 2 warp rows  (64 M each)
    const int wn = wid >> 1;       // 4 warp cols  (32 N each)
    const int m0 = blockIdx.y * BM;
    const int n0 = blockIdx.x * BN;

    float acc[4][4][4];
#pragma unroll
    for (int i = 0; i < 4; i++)
#pragma unroll
        for (int j = 0; j < 4; j++)
#pragma unroll
            for (int e = 0; e < 4; e++) acc[i][j][e] = 0.0f;

    // ldmatrix per-lane base byte offsets within a tile (row stride 128 B)
    const uint32_t a_base = (uint32_t)(wm * 64 + (lid & 15)) * 128 +
                            (uint32_t)(lid >> 4) * 16;
    const uint32_t b_base = (uint32_t)(wn * 32 + ((lid >> 3) & 2) * 4 + (lid & 7)) * 128 +
                            (uint32_t)((lid >> 3) & 1) * 16;

    // prologue: stages 0,1
#pragma unroll
    for (int p = 0; p < NSTAGES - 1; p++) {
        load_stage(sbase, p, p, m0, n0, tid);
        CP_ASYNC_COMMIT();
    }

    int st = 0;
    for (int kt = 0; kt < KITERS; kt++) {
        CP_ASYNC_WAIT(NSTAGES - 2);
        __syncthreads();

        // refill the stage freed one iteration ago (readers done pre-barrier)
        const int nk = kt + NSTAGES - 1;
        int nst = st - 1; if (nst < 0) nst += NSTAGES;
        if (nk < KITERS) load_stage(sbase, nst, nk, m0, n0, tid);
        CP_ASYNC_COMMIT();

        const uint32_t sA = sbase + st * STAGE_BYTES;
        const uint32_t sB = sA + TILE_BYTES;
#pragma unroll
        for (int ks = 0; ks < BK / 16; ks++) {   // 4 k16 steps
            uint32_t a[4][4];
#pragma unroll
            for (int mi = 0; mi < 4; mi++) {
                uint32_t o = a_base + (uint32_t)mi * (16 * 128) + (uint32_t)ks * 32;
                ldsm_x4(a[mi][0], a[mi][1], a[mi][2], a[mi][3], sA + SWZ(o));
            }
            uint32_t b[4][2];
#pragma unroll
            for (int p = 0; p < 2; p++) {  // each covers n-frags 2p, 2p+1
                uint32_t o = b_base + (uint32_t)p * (16 * 128) + (uint32_t)ks * 32;
                uint32_t r0, r1, r2, r3;
                ldsm_x4(r0, r1, r2, r3, sB + SWZ(o));
                b[2 * p][0] = r0; b[2 * p][1] = r1;
                b[2 * p + 1][0] = r2; b[2 * p + 1][1] = r3;
            }
#pragma unroll
            for (int mi = 0; mi < 4; mi++)
#pragma unroll
                for (int ni = 0; ni < 4; ni++)
                    mma16816(acc[mi][ni][0], acc[mi][ni][1],
                             acc[mi][ni][2], acc[mi][ni][3],
                             a[mi][0], a[mi][1], a[mi][2], a[mi][3],
                             b[ni][0], b[ni][1]);
        }
        st++; if (st == NSTAGES) st = 0;
    }

    // epilogue: fused bias, fp32 stores
    const int tr = lid >> 2;       // 0..7
    const int tc = lid & 3;        // 0..3
    const int mb = m0 + wm * 64;
    const int nb = n0 + wn * 32;
    float2 bv[4];
#pragma unroll
    for (int ni = 0; ni < 4; ni++)
        bv[ni] = *reinterpret_cast<const float2*>(bias + nb + ni * 8 + tc * 2);
#pragma unroll
    for (int mi = 0; mi < 4; mi++) {
        float* r0 = out + (size_t)(mb + mi * 16 + tr) * O_DIM + nb;
        float* r1 = r0 + (size_t)8 * O_DIM;
#pragma unroll
        for (int ni = 0; ni < 4; ni++) {
            float2 v0, v1;
            v0.x = acc[mi][ni][0] + bv[ni].x;
            v0.y = acc[mi][ni][1] + bv[ni].y;
            v1.x = acc[mi][ni][2] + bv[ni].x;
            v1.y = acc[mi][ni][3] + bv[ni].y;
            *reinterpret_cast<float2*>(r0 + ni * 8 + tc * 2) = v0;
            *reinterpret_cast<float2*>(r1 + ni * 8 + tc * 2) = v1;
        }
    }
}

// ---------------------------------------------------------------------------
// Launch
// ---------------------------------------------------------------------------
extern "C" void kernel_launch(void* const* d_in, const int* in_sizes, int n_in,
                              void* d_out, int out_size) {
    const float* x      = (const float*)d_in[0];  // [16,1024,1152]
    const float* w      = (const float*)d_in[1];  // [4608,1152]
    const float* smooth = (const float*)d_in[2];  // [1152]
    const float* bias   = (const float*)d_in[3];  // [4608]
    float* out = (float*)d_out;                   // [16,1024,4608]

    prep_kernel<<<QBLKS + WCONV_BLOCKS, 256>>>(x, smooth, w);

    cudaFuncSetAttribute(gemm_kernel, cudaFuncAttributeMaxDynamicSharedMemorySize,
                         SMEM_TOTAL);
    dim3 grid(O_DIM / BN, T_TOK / BM);   // (36, 128)
    gemm_kernel<<<grid, 256, SMEM_TOTAL>>>(bias, out);
}